// round 11
// baseline (speedup 1.0000x reference)
#include <cuda_runtime.h>
#include <math.h>

// SpikeToCalciumDoubleExp via warp-parallel weighted scan (no shared memory).
//
// out[t] = A'[s] - B'[s],  s = t+K-1  (1/scale folded into both states)
//   A'[s] = a*A'[s-1] + ia*u[s] - iaK1*u[s-K]   (exact finite window)
//   B'[s] = b*B'[s-1] + ib*u[s]                  (b^{K+1} = e^{-61} ~ 3e-27: lag dropped)
//
// Radix-8 lanes: each step covers 256 outputs (8/lane). A-scan: 5 stages
// (ratios a^8..a^128; a^128 ~ 1.7e-3 NOT droppable). B-scan: 2 stages
// (dropped weight b^32 = e^{-16} ~ 1.1e-7); B carry factor truncated at
// lane >= 4. Lane Horner = two 4-chains + combine (depth 4).
//
// R10 -> R11: register-forwarded lag stream. In steady state the lag octet
// u[tb+8L .. +8) of lane L is already in warp registers:
//   L >= 15: current x-octet of lane L-15   (u[tb+120+8(L-15)+j] = u[tb+8L+j])
//   L <= 14: previous step's x-octet of lane L+17
// Both collapse to y_j = shfl(w_j, (lane+17)&31), w_j = lane<=16 ? x_j : px_j.
// Lane0's l0 = u[tb-1] = px_7 of lane 16. Deletes 2 LDG.128 + 1 scalar LDG
// per step (the L1-wavefront pole at 68% in R10); values bit-identical.

#define WARPS_PER_CTA 8
#define THREADS_SCAN (WARPS_PER_CTA * 32)
#define STEP_OUT 256                    // outputs per warp step (8 per lane)
#define STEPS_PER_SEG 10
#define SEG_LEN (STEP_OUT * STEPS_PER_SEG)   // 2560 outputs per warp segment

struct StcConsts {
    float a, b, a4, b4, ia, ib, iaK1;
    float mA1, mA2, mA4, mA8, mA16, nB1, nB2;
    float a8l, b8l;
};

template<bool FIRST, bool PARTIAL>
__device__ __forceinline__ void stc_step8(
    const float* __restrict__ urow, float* __restrict__ orow,
    const int tb, const int t_end, const int lane, const int Km1,
    const StcConsts& c, float (&px)[8],
    float& carryA, float& carryB)
{
    const unsigned FULL = 0xffffffffu;
    const int tl = tb + 8 * lane;                 // first output t of this lane
    const bool v = !PARTIAL || (tl < t_end);      // T_out%8==0 -> whole 8-chunk valid

    float x[8];
    #pragma unroll
    for (int j = 0; j < 8; ++j) x[j] = 0.f;
    if (v) {
        const float4 xa = *(const float4*)(urow + tl + Km1);
        const float4 xb = *(const float4*)(urow + tl + Km1 + 4);
        x[0]=xa.x; x[1]=xa.y; x[2]=xa.z; x[3]=xa.w;
        x[4]=xb.x; x[5]=xb.y; x[6]=xb.z; x[7]=xb.w;
    }

    // lag octet y_j = u[tl + j]
    float y[8];
    if (FIRST) {
        #pragma unroll
        for (int j = 0; j < 8; ++j) y[j] = 0.f;
        if (v) {
            const float4 ya = *(const float4*)(urow + tl);
            const float4 yb = *(const float4*)(urow + tl + 4);
            y[0]=ya.x; y[1]=ya.y; y[2]=ya.z; y[3]=ya.w;
            y[4]=yb.x; y[5]=yb.y; y[6]=yb.z; y[7]=yb.w;
        }
    } else {
        const int src = (lane + 17) & 31;
        #pragma unroll
        for (int j = 0; j < 8; ++j) {
            const float w = (lane <= 16) ? x[j] : px[j];
            y[j] = __shfl_sync(FULL, w, src);
        }
    }

    // l0 = u[tl - 1]: lanes>=1 from neighbor's y[7]; lane0 from px_7 of lane16
    float l0 = __shfl_up_sync(FULL, y[7], 1);
    if (FIRST) {
        if (lane == 0) l0 = 0.f;   // exact: cancels against omitted carry term
    } else {
        const float l0lane0 = __shfl_sync(FULL, px[7], 16);  // u[tb-1]
        if (lane == 0) l0 = l0lane0;
    }

    const float ca0 = fmaf(c.ia, x[0], -(c.iaK1 * l0));
    const float ca1 = fmaf(c.ia, x[1], -(c.iaK1 * y[0]));
    const float ca2 = fmaf(c.ia, x[2], -(c.iaK1 * y[1]));
    const float ca3 = fmaf(c.ia, x[3], -(c.iaK1 * y[2]));
    const float ca4 = fmaf(c.ia, x[4], -(c.iaK1 * y[3]));
    const float ca5 = fmaf(c.ia, x[5], -(c.iaK1 * y[4]));
    const float ca6 = fmaf(c.ia, x[6], -(c.iaK1 * y[5]));
    const float ca7 = fmaf(c.ia, x[7], -(c.iaK1 * y[6]));
    const float cb0 = c.ib*x[0], cb1 = c.ib*x[1], cb2 = c.ib*x[2], cb3 = c.ib*x[3];
    const float cb4 = c.ib*x[4], cb5 = c.ib*x[5], cb6 = c.ib*x[6], cb7 = c.ib*x[7];

    // lane aggregates: two 4-chains combined (depth 4, not 7)
    const float SAh = fmaf(c.a, fmaf(c.a, fmaf(c.a, ca0, ca1), ca2), ca3);
    const float SAl = fmaf(c.a, fmaf(c.a, fmaf(c.a, ca4, ca5), ca6), ca7);
    float SA = fmaf(c.a4, SAh, SAl);
    const float SBh = fmaf(c.b, fmaf(c.b, fmaf(c.b, cb0, cb1), cb2), cb3);
    const float SBl = fmaf(c.b, fmaf(c.b, fmaf(c.b, cb4, cb5), cb6), cb7);
    float SB = fmaf(c.b4, SBh, SBl);

    // inclusive Kogge-Stone weighted scan across lanes, chunk ratio a^8 (b^8)
    float t;
    t = __shfl_up_sync(FULL, SA, 1);  if (lane >= 1)  SA = fmaf(c.mA1,  t, SA);
    t = __shfl_up_sync(FULL, SA, 2);  if (lane >= 2)  SA = fmaf(c.mA2,  t, SA);
    t = __shfl_up_sync(FULL, SA, 4);  if (lane >= 4)  SA = fmaf(c.mA4,  t, SA);
    t = __shfl_up_sync(FULL, SA, 8);  if (lane >= 8)  SA = fmaf(c.mA8,  t, SA);
    t = __shfl_up_sync(FULL, SA, 16); if (lane >= 16) SA = fmaf(c.mA16, t, SA);
    t = __shfl_up_sync(FULL, SB, 1);  if (lane >= 1)  SB = fmaf(c.nB1,  t, SB);
    t = __shfl_up_sync(FULL, SB, 2);  if (lane >= 2)  SB = fmaf(c.nB2,  t, SB);
    // exclusive
    float EA = __shfl_up_sync(FULL, SA, 1); EA = (lane >= 1) ? EA : 0.f;
    float EB = __shfl_up_sync(FULL, SB, 1); EB = (lane >= 1) ? EB : 0.f;

    // state entering this lane's chunk, then intra-lane chains
    const float PreA = fmaf(c.a8l, carryA, EA);
    const float PreB = fmaf(c.b8l, carryB, EB);
    const float A0 = fmaf(c.a, PreA, ca0);
    const float A1 = fmaf(c.a, A0, ca1);
    const float A2 = fmaf(c.a, A1, ca2);
    const float A3 = fmaf(c.a, A2, ca3);
    const float A4 = fmaf(c.a, A3, ca4);
    const float A5 = fmaf(c.a, A4, ca5);
    const float A6 = fmaf(c.a, A5, ca6);
    const float A7 = fmaf(c.a, A6, ca7);
    const float B0 = fmaf(c.b, PreB, cb0);
    const float B1 = fmaf(c.b, B0, cb1);
    const float B2 = fmaf(c.b, B1, cb2);
    const float B3 = fmaf(c.b, B2, cb3);
    const float B4 = fmaf(c.b, B3, cb4);
    const float B5 = fmaf(c.b, B4, cb5);
    const float B6 = fmaf(c.b, B5, cb6);
    const float B7 = fmaf(c.b, B6, cb7);

    carryA = __shfl_sync(FULL, A7, 31);
    carryB = __shfl_sync(FULL, B7, 31);

    if (v) {
        float4 oa, ob;
        oa.x = A0 - B0; oa.y = A1 - B1; oa.z = A2 - B2; oa.w = A3 - B3;
        ob.x = A4 - B4; ob.y = A5 - B5; ob.z = A6 - B6; ob.w = A7 - B7;
        *(float4*)(orow + tl)     = oa;
        *(float4*)(orow + tl + 4) = ob;
    }

    // carry this step's x-octet to the next step (renamed away under unroll)
    #pragma unroll
    for (int j = 0; j < 8; ++j) px[j] = x[j];
}

__global__ __launch_bounds__(THREADS_SCAN, 4)
void stc_scan_kernel(const float* __restrict__ u, float* __restrict__ out,
                     float a, float b, float ia, float ib, float iaK1, float inv_scale,
                     float l2a, float l2b,
                     int K, int T_in, int T_out, int segs_per_row, int total_segs)
{
    const int lane = threadIdx.x & 31;
    const int gseg = blockIdx.x * WARPS_PER_CTA + (threadIdx.x >> 5);
    if (gseg >= total_segs) return;
    const int row = gseg / segs_per_row;
    const int seg = gseg - row * segs_per_row;
    const int t0 = seg * SEG_LEN;
    const int t_end = min(t0 + SEG_LEN, T_out);
    const float* __restrict__ urow = u + (long long)row * T_in;
    float* __restrict__ orow = out + (long long)row * T_out;
    const int Km1 = K - 1;

    StcConsts c;
    {
        const float a2 = a*a, b2 = b*b;
        c.a = a; c.b = b;
        c.a4 = a2*a2; c.b4 = b2*b2;
        c.ia = ia; c.ib = ib; c.iaK1 = iaK1;
        const float a8 = c.a4*c.a4, b8 = c.b4*c.b4;
        c.mA1 = a8; c.mA2 = a8*a8; c.mA4 = c.mA2*c.mA2;
        c.mA8 = c.mA4*c.mA4; c.mA16 = c.mA8*c.mA8;
        c.nB1 = b8; c.nB2 = b8*b8;                 // stage 3 dropped: b^32 ~ 1.1e-7
        c.a8l = exp2f(l2a * (float)(8 * lane));
        c.b8l = (lane < 4) ? exp2f(l2b * (float)(8 * lane)) : 0.f;
    }

    // ---- segment-start carry: inv_scale * sum_{i=0}^{K-2} p^{K-1-i} u[t0+i] ----
    float carryA, carryB;
    {
        const int i0 = 4 * lane;
        float Pa = 0.f, Pb = 0.f, wA = 0.f, wB = 0.f;
        if (i0 <= Km1 - 1) {
            float x0, x1 = 0.f, x2 = 0.f, x3 = 0.f;
            if (i0 + 3 <= Km1 - 1) {
                const float4 vv = *(const float4*)(urow + t0 + i0);
                x0 = vv.x; x1 = vv.y; x2 = vv.z; x3 = vv.w;
            } else {
                x0 = urow[t0 + i0];
                if (i0 + 1 <= Km1 - 1) x1 = urow[t0 + i0 + 1];
                if (i0 + 2 <= Km1 - 1) x2 = urow[t0 + i0 + 2];
            }
            Pa = fmaf(a, fmaf(a, fmaf(a, x0, x1), x2), x3);
            Pb = fmaf(b, fmaf(b, fmaf(b, x0, x1), x2), x3);
            wA = exp2f(l2a * (float)(K - 4 - i0)) * inv_scale;
            wB = exp2f(l2b * (float)(K - 4 - i0)) * inv_scale;
        }
        float qa = wA * Pa, qb = wB * Pb;
        #pragma unroll
        for (int k = 16; k >= 1; k >>= 1) {
            qa += __shfl_xor_sync(0xffffffffu, qa, k);
            qb += __shfl_xor_sync(0xffffffffu, qb, k);
        }
        carryA = qa; carryB = qb;
    }

    // ---- steps ----
    float px[8];
    #pragma unroll
    for (int j = 0; j < 8; ++j) px[j] = 0.f;

    int tb = t0;
    if (tb + STEP_OUT <= t_end) {
        stc_step8<true, false>(urow, orow, tb, t_end, lane, Km1, c, px, carryA, carryB);
    } else {
        stc_step8<true, true >(urow, orow, tb, t_end, lane, Km1, c, px, carryA, carryB);
    }
    tb += STEP_OUT;
    // unroll 2: lets ptxas ping-pong px/x registers and hoist the next step's
    // (address-independent) LDGs above the current shuffle/FMA chain.
    #pragma unroll 2
    for (; tb + STEP_OUT <= t_end; tb += STEP_OUT)
        stc_step8<false, false>(urow, orow, tb, t_end, lane, Km1, c, px, carryA, carryB);
    if (tb < t_end)
        stc_step8<false, true >(urow, orow, tb, t_end, lane, Km1, c, px, carryA, carryB);
}

// Correctness-only fallback for shapes the fast path doesn't cover.
__global__ void stc_fallback_kernel(const float* __restrict__ u, float* __restrict__ out,
                                    float a, float b, float inv_scale,
                                    int K, int T_in, int T_out, long long total)
{
    const long long idx = (long long)blockIdx.x * blockDim.x + threadIdx.x;
    if (idx >= total) return;
    const int row = (int)(idx / T_out);
    const int t   = (int)(idx - (long long)row * T_out);
    const float* p = u + (long long)row * T_in + t;
    float A = 0.f, B = 0.f;
    for (int m = 0; m < K; ++m) {
        const float x = p[m];
        A = fmaf(a, A, x);
        B = fmaf(b, B, x);
    }
    out[idx] = (a * A - b * B) * inv_scale;
}

extern "C" void kernel_launch(void* const* d_in, const int* in_sizes, int n_in,
                              void* d_out, int out_size)
{
    const float* u = (const float*)d_in[0];
    const int K = (n_in > 1) ? in_sizes[1] : 121;

    // rows * T_in = in_sizes[0]; rows * T_out = out_size; T_in - T_out = K - 1
    const long long total_in = (long long)in_sizes[0];
    int rows = 1;
    if (K > 1) {
        const long long diff = total_in - (long long)out_size;
        if (diff > 0 && diff % (K - 1) == 0) {
            const long long r = diff / (K - 1);
            if (r > 0 && total_in % r == 0 && out_size % r == 0) rows = (int)r;
        }
    }
    const int T_in  = (int)(total_in / rows);
    const int T_out = out_size / rows;

    // Constants from the reference formula (HZ=20, TAU1=1.0, TAU2=0.1)
    const double tau1 = 1.0 * 20.0;
    const double tau2 = 0.1 * 20.0;
    const double a = exp(-1.0 / tau1);
    const double b = exp(-1.0 / tau2);
    const double r = tau1 / tau2;
    const double d = tau1 - tau2;
    const double scale = pow(r, -tau2 / d) - pow(r, -tau1 / d);
    const double inv = 1.0 / scale;

    const float fa   = (float)a;
    const float fb   = (float)b;
    const float ia   = (float)(a * inv);                       // a/scale
    const float ib   = (float)(b * inv);                       // b/scale
    const float iaK1 = (float)(pow(a, (double)(K + 1)) * inv); // a^{K+1}/scale
    const float finv = (float)inv;
    const float l2a  = (float)(log(a) / log(2.0));
    const float l2b  = (float)(log(b) / log(2.0));

    const bool fast = (K >= 6) && ((K - 1) % 4 == 0) && (K - 1 <= 128) &&
                      (T_in % 4 == 0) && (T_out % 8 == 0);

    if (fast) {
        const int segs_per_row = (T_out + SEG_LEN - 1) / SEG_LEN;
        const int total_segs   = rows * segs_per_row;
        const int blocks = (total_segs + WARPS_PER_CTA - 1) / WARPS_PER_CTA;
        stc_scan_kernel<<<blocks, THREADS_SCAN>>>(
            u, (float*)d_out, fa, fb, ia, ib, iaK1, finv, l2a, l2b,
            K, T_in, T_out, segs_per_row, total_segs);
    } else {
        const long long total = (long long)rows * T_out;
        const int blocks = (int)((total + 255) / 256);
        stc_fallback_kernel<<<blocks, 256>>>(
            u, (float*)d_out, fa, fb, finv, K, T_in, T_out, total);
    }
}